// round 7
// baseline (speedup 1.0000x reference)
#include <cuda_runtime.h>
#include <cstdint>

// ============================================================================
// Induction capsule routing, restructured (no e materialization):
//   c_i = (sum_s d_is x_is) @ W      (u_kernel; gemm NT: B=W, k-rows j-contig)
//   b  += x . (W c)                  (gemm TN: B=W, j-rows k-contig; b_update)
// Split-K GEMM on mma.sync m16n8k8 tf32, 3xTF32 split PRE-COMPUTED at staging
// (smem holds interleaved {hi,lo} pairs) -> inner loop is pure LDS + HMMA.
// ============================================================================

static constexpr int C_CAPS = 64;
static constexpr int S_LEN  = 128;
static constexpr int H_DIM  = 2048;
static constexpr int KSPLIT = 16;
static constexpr int KLEN   = H_DIM / KSPLIT;   // 128 (8 chunks of 16)
static constexpr int NCHUNK = KLEN / 16;        // 8
static constexpr int P2     = 20;               // smem pitch in float2 (160B rows)

// ---- scratch (device globals; allocation-free rule) ----
__device__ float g_b[C_CAPS * S_LEN];                       // logits
__device__ float g_u[C_CAPS * H_DIM];                       // weighted x sums
__device__ float g_v[C_CAPS * H_DIM];                       // W @ c
__device__ float g_part[KSPLIT][C_CAPS][H_DIM];             // split-K partials (8 MB)
__device__ float g_nrm2[C_CAPS][4];                         // per-block norm partials

__global__ void zero_b_kernel() {
    int i = blockIdx.x * blockDim.x + threadIdx.x;
    if (i < C_CAPS * S_LEN) g_b[i] = 0.0f;
}

// ============================================================================
// u_kernel: d = softmax(b[cap,:]); u[cap,h] = sum_s d[s] * x[cap,s,h]
// ============================================================================
__global__ void __launch_bounds__(256) u_kernel(const float* __restrict__ x) {
    const int cap = blockIdx.y;
    const int tid = threadIdx.x;
    const int h = blockIdx.x * 256 + tid;
    __shared__ float d[S_LEN];

    if (tid < S_LEN) d[tid] = g_b[cap * S_LEN + tid];
    __syncthreads();
    if (tid < 32) {
        float x0 = d[tid], x1 = d[tid + 32], x2 = d[tid + 64], x3 = d[tid + 96];
        float mx = fmaxf(fmaxf(x0, x1), fmaxf(x2, x3));
        #pragma unroll
        for (int o = 16; o > 0; o >>= 1) mx = fmaxf(mx, __shfl_xor_sync(0xffffffffu, mx, o));
        float e0 = __expf(x0 - mx), e1 = __expf(x1 - mx);
        float e2 = __expf(x2 - mx), e3 = __expf(x3 - mx);
        float s = (e0 + e1) + (e2 + e3);
        #pragma unroll
        for (int o = 16; o > 0; o >>= 1) s += __shfl_xor_sync(0xffffffffu, s, o);
        float inv = 1.0f / s;
        d[tid] = e0 * inv; d[tid + 32] = e1 * inv; d[tid + 64] = e2 * inv; d[tid + 96] = e3 * inv;
    }
    __syncthreads();

    const float* xp = x + (size_t)cap * S_LEN * H_DIM + h;
    float a0 = 0.f, a1 = 0.f, a2 = 0.f, a3 = 0.f;
    #pragma unroll 8
    for (int s = 0; s < S_LEN; s += 4) {
        a0 = fmaf(d[s + 0], xp[(size_t)(s + 0) * H_DIM], a0);
        a1 = fmaf(d[s + 1], xp[(size_t)(s + 1) * H_DIM], a1);
        a2 = fmaf(d[s + 2], xp[(size_t)(s + 2) * H_DIM], a2);
        a3 = fmaf(d[s + 3], xp[(size_t)(s + 3) * H_DIM], a3);
    }
    g_u[cap * H_DIM + h] = (a0 + a1) + (a2 + a3);
}

// ============================================================================
// 3xTF32 helpers
// ============================================================================
static __device__ __forceinline__ float2 tf32_split2(float f) {
    uint32_t hi, lo;
    asm("cvt.rna.tf32.f32 %0, %1;" : "=r"(hi) : "f"(f));
    float r = f - __uint_as_float(hi);
    asm("cvt.rna.tf32.f32 %0, %1;" : "=r"(lo) : "f"(r));
    return make_float2(__uint_as_float(hi), __uint_as_float(lo));
}
static __device__ __forceinline__ void mma_tf32(float* c, const uint32_t* a,
                                                uint32_t b0, uint32_t b1) {
    asm("mma.sync.aligned.m16n8k8.row.col.f32.tf32.tf32.f32 "
        "{%0,%1,%2,%3}, {%4,%5,%6,%7}, {%8,%9}, {%0,%1,%2,%3};"
        : "+f"(c[0]), "+f"(c[1]), "+f"(c[2]), "+f"(c[3])
        : "r"(a[0]), "r"(a[1]), "r"(a[2]), "r"(a[3]), "r"(b0), "r"(b1));
}

// ============================================================================
// gemm_mma<BK_CONTIG>: g_part[kz][m][j] = sum_{k in chunk kz} A[m][k]*Bval(k,j)
//   BK_CONTIG=true  (TN): Bval(k,j) = B[(j0+j)*H + k]      (v = c @ W^T)
//   BK_CONTIG=false (NT): Bval(k,j) = B[k*H + (j0+j)]      (c = u @ W)
//   grid (32, 16) = 512 CTAs, block 128 (4 warps).
//   Smem: interleaved {hi,lo} float2, pitch P2. Inner loop: LDS.64 + HMMA only.
// ============================================================================
template <bool BK_CONTIG>
__global__ void __launch_bounds__(128) gemm_mma_kernel(const float* __restrict__ A,
                                                       const float* __restrict__ B) {
    __shared__ float2 As2[2][64][P2];
    __shared__ float2 Bs2[2][64][P2];

    const int tid = threadIdx.x;
    const int lane = tid & 31;
    const int w = tid >> 5;
    const int j0 = blockIdx.x * 64;
    const int kz = blockIdx.y;
    const int k0 = kz * KLEN;

    // ---- staging slots (2 per thread for each of A, B) ----
    const int am0 = tid >> 2,           ak0 = (tid & 3) * 4;
    const int am1 = (tid + 128) >> 2,   ak1 = ((tid + 128) & 3) * 4;
    const float* ap0 = A + (size_t)am0 * H_DIM + k0 + ak0;
    const float* ap1 = A + (size_t)am1 * H_DIM + k0 + ak1;

    int br0, bg0, br1, bg1;
    const float *bp0, *bp1;
    if (BK_CONTIG) {            // B[j][k]: 64 j-rows x 4 k-groups
        br0 = tid >> 2;          bg0 = (tid & 3) * 4;
        br1 = (tid + 128) >> 2;  bg1 = ((tid + 128) & 3) * 4;
        bp0 = B + (size_t)(j0 + br0) * H_DIM + k0 + bg0;
        bp1 = B + (size_t)(j0 + br1) * H_DIM + k0 + bg1;
    } else {                    // B[k][j]: 16 k-rows x 16 j-groups
        br0 = tid >> 4;          bg0 = (tid & 15) * 4;
        br1 = (tid + 128) >> 4;  bg1 = ((tid + 128) & 15) * 4;
        bp0 = B + (size_t)(k0 + br0) * H_DIM + j0 + bg0;
        bp1 = B + (size_t)(k0 + br1) * H_DIM + j0 + bg1;
    }

    // prologue: chunk 0 global loads
    float4 ar0 = *(const float4*)ap0, ar1 = *(const float4*)ap1;
    float4 br0v = *(const float4*)bp0, br1v = *(const float4*)bp1;

    const int g = lane >> 2, t = lane & 3;
    const int mrow = w * 16 + g;

    float acc[8][4] = {};

    for (int kc = 0; kc < NCHUNK; kc++) {
        const int cur = kc & 1;
        // split + store (hi,lo) pairs; k..k+3 are 4 consecutive float2 = 2 float4
        {
            float2 s0 = tf32_split2(ar0.x), s1 = tf32_split2(ar0.y);
            float2 s2 = tf32_split2(ar0.z), s3 = tf32_split2(ar0.w);
            float4* d0 = (float4*)&As2[cur][am0][ak0];
            d0[0] = make_float4(s0.x, s0.y, s1.x, s1.y);
            d0[1] = make_float4(s2.x, s2.y, s3.x, s3.y);
            s0 = tf32_split2(ar1.x); s1 = tf32_split2(ar1.y);
            s2 = tf32_split2(ar1.z); s3 = tf32_split2(ar1.w);
            float4* d1 = (float4*)&As2[cur][am1][ak1];
            d1[0] = make_float4(s0.x, s0.y, s1.x, s1.y);
            d1[1] = make_float4(s2.x, s2.y, s3.x, s3.y);
        }
        if (BK_CONTIG) {
            float2 s0 = tf32_split2(br0v.x), s1 = tf32_split2(br0v.y);
            float2 s2 = tf32_split2(br0v.z), s3 = tf32_split2(br0v.w);
            float4* d0 = (float4*)&Bs2[cur][br0][bg0];
            d0[0] = make_float4(s0.x, s0.y, s1.x, s1.y);
            d0[1] = make_float4(s2.x, s2.y, s3.x, s3.y);
            s0 = tf32_split2(br1v.x); s1 = tf32_split2(br1v.y);
            s2 = tf32_split2(br1v.z); s3 = tf32_split2(br1v.w);
            float4* d1 = (float4*)&Bs2[cur][br1][bg1];
            d1[0] = make_float4(s0.x, s0.y, s1.x, s1.y);
            d1[1] = make_float4(s2.x, s2.y, s3.x, s3.y);
        } else {
            // 4 j's for one k: scatter 4 float2 stores to Bs2[j][k]
            Bs2[cur][bg0 + 0][br0] = tf32_split2(br0v.x);
            Bs2[cur][bg0 + 1][br0] = tf32_split2(br0v.y);
            Bs2[cur][bg0 + 2][br0] = tf32_split2(br0v.z);
            Bs2[cur][bg0 + 3][br0] = tf32_split2(br0v.w);
            Bs2[cur][bg1 + 0][br1] = tf32_split2(br1v.x);
            Bs2[cur][bg1 + 1][br1] = tf32_split2(br1v.y);
            Bs2[cur][bg1 + 2][br1] = tf32_split2(br1v.z);
            Bs2[cur][bg1 + 3][br1] = tf32_split2(br1v.w);
        }
        __syncthreads();

        if (kc + 1 < NCHUNK) {
            const int ko = (kc + 1) * 16;
            ar0 = *(const float4*)(ap0 + ko);
            ar1 = *(const float4*)(ap1 + ko);
            if (BK_CONTIG) {
                br0v = *(const float4*)(bp0 + ko);
                br1v = *(const float4*)(bp1 + ko);
            } else {
                br0v = *(const float4*)(bp0 + (size_t)ko * H_DIM);
                br1v = *(const float4*)(bp1 + (size_t)ko * H_DIM);
            }
        }

        #pragma unroll
        for (int kk = 0; kk < 16; kk += 8) {
            // A fragment: 4 LDS.64 gets {hi,lo} in one shot
            float2 pa0 = As2[cur][mrow    ][kk + t];
            float2 pa1 = As2[cur][mrow + 8][kk + t];
            float2 pa2 = As2[cur][mrow    ][kk + t + 4];
            float2 pa3 = As2[cur][mrow + 8][kk + t + 4];
            uint32_t ah[4] = {__float_as_uint(pa0.x), __float_as_uint(pa1.x),
                              __float_as_uint(pa2.x), __float_as_uint(pa3.x)};
            uint32_t al[4] = {__float_as_uint(pa0.y), __float_as_uint(pa1.y),
                              __float_as_uint(pa2.y), __float_as_uint(pa3.y)};
            #pragma unroll
            for (int nt = 0; nt < 8; nt++) {
                float2 pb0 = Bs2[cur][nt * 8 + g][kk + t];
                float2 pb1 = Bs2[cur][nt * 8 + g][kk + t + 4];
                uint32_t bh0 = __float_as_uint(pb0.x), bl0 = __float_as_uint(pb0.y);
                uint32_t bh1 = __float_as_uint(pb1.x), bl1 = __float_as_uint(pb1.y);
                mma_tf32(acc[nt], al, bh0, bh1);   // lo*hi
                mma_tf32(acc[nt], ah, bl0, bl1);   // hi*lo
                mma_tf32(acc[nt], ah, bh0, bh1);   // hi*hi
            }
        }
        // single barrier per chunk: next store targets the other buffer whose
        // readers all finished before THIS chunk's barrier.
    }

    // epilogue: c0=(g,2t) c1=(g,2t+1) c2=(g+8,2t) c3=(g+8,2t+1) per n-tile
    #pragma unroll
    for (int nt = 0; nt < 8; nt++) {
        const int col = j0 + nt * 8 + 2 * t;
        *(float2*)&g_part[kz][mrow    ][col] = make_float2(acc[nt][0], acc[nt][1]);
        *(float2*)&g_part[kz][mrow + 8][col] = make_float2(acc[nt][2], acc[nt][3]);
    }
}

// ============================================================================
// reduce_c_norm: out[cap][j] = sum_z g_part[z][cap][j] (float4/thread);
//                g_nrm2[cap][jb] = partial ||row||^2.  grid (4, 64), block 128.
// ============================================================================
__global__ void __launch_bounds__(128) reduce_c_norm_kernel(float* __restrict__ out) {
    const int cap = blockIdx.y;
    const int jb = blockIdx.x;
    const int tid = threadIdx.x;
    const int j = (jb * 128 + tid) * 4;

    float4 a = make_float4(0.f, 0.f, 0.f, 0.f);
    #pragma unroll
    for (int z = 0; z < KSPLIT; z++) {
        float4 p = *(const float4*)&g_part[z][cap][j];
        a.x += p.x; a.y += p.y; a.z += p.z; a.w += p.w;
    }
    *(float4*)(out + cap * H_DIM + j) = a;

    float sq = a.x * a.x + a.y * a.y + a.z * a.z + a.w * a.w;
    #pragma unroll
    for (int o = 16; o > 0; o >>= 1) sq += __shfl_xor_sync(0xffffffffu, sq, o);
    __shared__ float ws[4];
    if ((tid & 31) == 0) ws[tid >> 5] = sq;
    __syncthreads();
    if (tid == 0) g_nrm2[cap][jb] = (ws[0] + ws[1]) + (ws[2] + ws[3]);
}

// ============================================================================
// squash_scale: coeff from 4 norm partials; scale out row in place. grid 64.
// ============================================================================
__global__ void __launch_bounds__(256) squash_scale_kernel(float* __restrict__ out) {
    const int cap = blockIdx.x;
    const int tid = threadIdx.x;
    __shared__ float coeff_s;
    if (tid == 0) {
        float s = (g_nrm2[cap][0] + g_nrm2[cap][1]) + (g_nrm2[cap][2] + g_nrm2[cap][3]);
        coeff_s = s / (1.0f + s) / sqrtf(s + 1e-9f);
    }
    __syncthreads();
    const float co = coeff_s;
    float* row = out + cap * H_DIM;
    #pragma unroll
    for (int r = 0; r < 2; r++) {
        int j = (tid + 256 * r) * 4;
        float4 v = *(float4*)(row + j);
        *(float4*)(row + j) = make_float4(v.x * co, v.y * co, v.z * co, v.w * co);
    }
}

// ============================================================================
// reduce_v: v[m][j] = sum_z g_part[z][m][j]   (grid 128, block 256, float4)
// ============================================================================
__global__ void __launch_bounds__(256) reduce_v_kernel() {
    const int idx4 = blockIdx.x * 256 + threadIdx.x;   // 0 .. 32767
    const int m = idx4 >> 9;
    const int j = (idx4 & 511) * 4;
    float4 a = make_float4(0.f, 0.f, 0.f, 0.f);
    #pragma unroll
    for (int z = 0; z < KSPLIT; z++) {
        float4 p = *(const float4*)&g_part[z][m][j];
        a.x += p.x; a.y += p.y; a.z += p.z; a.w += p.w;
    }
    *(float4*)&g_v[m * H_DIM + j] = a;
}

// ============================================================================
// b_update: b[cap,s] += x[cap,s,:] . v[cap,:]   (warp per s; v staged in smem)
// ============================================================================
__global__ void __launch_bounds__(256) b_update_kernel(const float* __restrict__ x) {
    const int cap = blockIdx.y;
    const int tid = threadIdx.x;
    __shared__ float vs[H_DIM];
    #pragma unroll
    for (int j = 0; j < 2; j++) {
        float4 vv = *(const float4*)(g_v + cap * H_DIM + (tid + 256 * j) * 4);
        *(float4*)(vs + (tid + 256 * j) * 4) = vv;
    }
    __syncthreads();

    const int warp = tid >> 5, lane = tid & 31;
    const int s = blockIdx.x * 8 + warp;
    const float4* xp = (const float4*)(x + ((size_t)cap * S_LEN + s) * H_DIM);
    const float4* vp = (const float4*)vs;
    float acc = 0.f;
    #pragma unroll 4
    for (int j = lane; j < H_DIM / 4; j += 32) {
        float4 ev = xp[j], cv = vp[j];
        acc = fmaf(ev.x, cv.x, acc);
        acc = fmaf(ev.y, cv.y, acc);
        acc = fmaf(ev.z, cv.z, acc);
        acc = fmaf(ev.w, cv.w, acc);
    }
    #pragma unroll
    for (int o = 16; o > 0; o >>= 1) acc += __shfl_xor_sync(0xffffffffu, acc, o);
    if (lane == 0) g_b[cap * S_LEN + s] += acc;
}

// ============================================================================
// kernel_launch
// ============================================================================
extern "C" void kernel_launch(void* const* d_in, const int* in_sizes, int n_in,
                              void* d_out, int out_size) {
    const float* x = (const float*)d_in[0];   // [64,128,2048] fp32
    const float* W = (const float*)d_in[1];   // [2048,2048] fp32
    float* out = (float*)d_out;               // [64,2048] fp32 — holds c

    float* u_ptr;
    cudaGetSymbolAddress((void**)&u_ptr, g_u);

    const dim3 gemm_grid(H_DIM / 64, KSPLIT);

    zero_b_kernel<<<8, 1024>>>();

    for (int it = 0; it < 3; ++it) {
        u_kernel<<<dim3(H_DIM / 256, C_CAPS), 256>>>(x);
        gemm_mma_kernel<false><<<gemm_grid, 128>>>(u_ptr, W);        // c = u @ W
        reduce_c_norm_kernel<<<dim3(4, C_CAPS), 128>>>(out);
        squash_scale_kernel<<<C_CAPS, 256>>>(out);
        if (it < 2) {
            gemm_mma_kernel<true><<<gemm_grid, 128>>>(out, W);       // v = c @ W^T
            reduce_v_kernel<<<C_CAPS * H_DIM / 1024, 256>>>();
            b_update_kernel<<<dim3(S_LEN / 8, C_CAPS), 256>>>(x);
        }
    }
}

// round 8
// speedup vs baseline: 1.3939x; 1.3939x over previous
#include <cuda_runtime.h>
#include <cstdint>

// ============================================================================
// Induction capsule routing, restructured (no e materialization):
//   c_i = (sum_s d_is x_is) @ W      (u_kernel; gemm NT: B=W, k-rows j-contig)
//   b  += x . (W c)                  (gemm TN: B=W, j-rows k-contig; b_update)
// Split-K GEMM on mma.sync m16n8k8 tf32 with in-register 3xTF32 split.
// N-tile 32 -> 1024 CTAs for occupancy. Z-split vectorized reduces.
// ============================================================================

static constexpr int C_CAPS = 64;
static constexpr int S_LEN  = 128;
static constexpr int H_DIM  = 2048;
static constexpr int KSPLIT = 16;
static constexpr int KLEN   = H_DIM / KSPLIT;   // 128 (8 chunks of 16)
static constexpr int NCHUNK = KLEN / 16;        // 8
static constexpr int SP     = 20;               // smem row pitch (floats)

// ---- scratch (device globals; allocation-free rule) ----
__device__ float g_b[C_CAPS * S_LEN];                       // logits
__device__ float g_u[C_CAPS * H_DIM];                       // weighted x sums
__device__ float g_v[C_CAPS * H_DIM];                       // W @ c
__device__ float g_part[KSPLIT][C_CAPS][H_DIM];             // split-K partials (8 MB)
__device__ float g_nrm2[C_CAPS][16];                        // per-block norm partials

__global__ void zero_b_kernel() {
    int i = blockIdx.x * blockDim.x + threadIdx.x;
    if (i < C_CAPS * S_LEN) g_b[i] = 0.0f;
}

// ============================================================================
// u_kernel: d = softmax(b[cap,:]); u[cap,h] = sum_s d[s] * x[cap,s,h]
// ============================================================================
__global__ void __launch_bounds__(256) u_kernel(const float* __restrict__ x) {
    const int cap = blockIdx.y;
    const int tid = threadIdx.x;
    const int h = blockIdx.x * 256 + tid;
    __shared__ float d[S_LEN];

    if (tid < S_LEN) d[tid] = g_b[cap * S_LEN + tid];
    __syncthreads();
    if (tid < 32) {
        float x0 = d[tid], x1 = d[tid + 32], x2 = d[tid + 64], x3 = d[tid + 96];
        float mx = fmaxf(fmaxf(x0, x1), fmaxf(x2, x3));
        #pragma unroll
        for (int o = 16; o > 0; o >>= 1) mx = fmaxf(mx, __shfl_xor_sync(0xffffffffu, mx, o));
        float e0 = __expf(x0 - mx), e1 = __expf(x1 - mx);
        float e2 = __expf(x2 - mx), e3 = __expf(x3 - mx);
        float s = (e0 + e1) + (e2 + e3);
        #pragma unroll
        for (int o = 16; o > 0; o >>= 1) s += __shfl_xor_sync(0xffffffffu, s, o);
        float inv = 1.0f / s;
        d[tid] = e0 * inv; d[tid + 32] = e1 * inv; d[tid + 64] = e2 * inv; d[tid + 96] = e3 * inv;
    }
    __syncthreads();

    const float* xp = x + (size_t)cap * S_LEN * H_DIM + h;
    float a0 = 0.f, a1 = 0.f, a2 = 0.f, a3 = 0.f;
    #pragma unroll 8
    for (int s = 0; s < S_LEN; s += 4) {
        a0 = fmaf(d[s + 0], xp[(size_t)(s + 0) * H_DIM], a0);
        a1 = fmaf(d[s + 1], xp[(size_t)(s + 1) * H_DIM], a1);
        a2 = fmaf(d[s + 2], xp[(size_t)(s + 2) * H_DIM], a2);
        a3 = fmaf(d[s + 3], xp[(size_t)(s + 3) * H_DIM], a3);
    }
    g_u[cap * H_DIM + h] = (a0 + a1) + (a2 + a3);
}

// ============================================================================
// 3xTF32 helpers
// ============================================================================
static __device__ __forceinline__ void tf32_split(float f, uint32_t& hi, uint32_t& lo) {
    asm("cvt.rna.tf32.f32 %0, %1;" : "=r"(hi) : "f"(f));
    float r = f - __uint_as_float(hi);
    asm("cvt.rna.tf32.f32 %0, %1;" : "=r"(lo) : "f"(r));
}
static __device__ __forceinline__ void mma_tf32(float* c, const uint32_t* a,
                                                uint32_t b0, uint32_t b1) {
    asm("mma.sync.aligned.m16n8k8.row.col.f32.tf32.tf32.f32 "
        "{%0,%1,%2,%3}, {%4,%5,%6,%7}, {%8,%9}, {%0,%1,%2,%3};"
        : "+f"(c[0]), "+f"(c[1]), "+f"(c[2]), "+f"(c[3])
        : "r"(a[0]), "r"(a[1]), "r"(a[2]), "r"(a[3]), "r"(b0), "r"(b1));
}

// ============================================================================
// gemm_mma<BK_CONTIG>: g_part[kz][m][j] = sum_{k in chunk kz} A[m][k]*Bval(k,j)
//   BK_CONTIG=true  (TN): Bval(k,j) = B[(j0+j)*H + k]      (v = c @ W^T)
//   BK_CONTIG=false (NT): Bval(k,j) = B[k*H + (j0+j)]      (c = u @ W)
//   grid (64, 16) = 1024 CTAs, block 128 (4 warps).
//   CTA tile: M=64, N=32, K=128 in 8 chunks of 16; double-buffered smem.
//   Warp w -> m rows [16w,16w+16); 4 n-tiles of 8; 3 mma per (k8, n-tile).
// ============================================================================
template <bool BK_CONTIG>
__global__ void __launch_bounds__(128) gemm_mma_kernel(const float* __restrict__ A,
                                                       const float* __restrict__ B) {
    __shared__ float As[2][64][SP];
    __shared__ float Bs[2][32][SP];

    const int tid = threadIdx.x;
    const int lane = tid & 31;
    const int w = tid >> 5;
    const int j0 = blockIdx.x * 32;
    const int kz = blockIdx.y;
    const int k0 = kz * KLEN;

    // ---- staging slots: A 2/thread, B 1/thread ----
    const int am0 = tid >> 2,           ak0 = (tid & 3) * 4;
    const int am1 = (tid + 128) >> 2,   ak1 = ((tid + 128) & 3) * 4;
    const float* ap0 = A + (size_t)am0 * H_DIM + k0 + ak0;
    const float* ap1 = A + (size_t)am1 * H_DIM + k0 + ak1;

    int br0, bg0;
    const float* bp0;
    if (BK_CONTIG) {            // B[j][k]: 32 j-rows x 4 k-groups = 128 slots
        br0 = tid >> 2;          bg0 = (tid & 3) * 4;
        bp0 = B + (size_t)(j0 + br0) * H_DIM + k0 + bg0;
    } else {                    // B[k][j]: 16 k-rows x 8 j-groups = 128 slots
        br0 = tid >> 3;          bg0 = (tid & 7) * 4;
        bp0 = B + (size_t)(k0 + br0) * H_DIM + j0 + bg0;
    }

    // prologue: chunk 0
    float4 ar0 = *(const float4*)ap0, ar1 = *(const float4*)ap1;
    float4 br0v = *(const float4*)bp0;

    const int g = lane >> 2, t = lane & 3;
    const int mrow = w * 16 + g;

    float acc[4][4] = {};

    for (int kc = 0; kc < NCHUNK; kc++) {
        const int cur = kc & 1;
        *(float4*)&As[cur][am0][ak0] = ar0;
        *(float4*)&As[cur][am1][ak1] = ar1;
        if (BK_CONTIG) {
            *(float4*)&Bs[cur][br0][bg0] = br0v;
        } else {
            Bs[cur][bg0 + 0][br0] = br0v.x; Bs[cur][bg0 + 1][br0] = br0v.y;
            Bs[cur][bg0 + 2][br0] = br0v.z; Bs[cur][bg0 + 3][br0] = br0v.w;
        }
        __syncthreads();

        if (kc + 1 < NCHUNK) {
            const int ko = (kc + 1) * 16;
            ar0 = *(const float4*)(ap0 + ko);
            ar1 = *(const float4*)(ap1 + ko);
            br0v = BK_CONTIG ? *(const float4*)(bp0 + ko)
                             : *(const float4*)(bp0 + (size_t)ko * H_DIM);
        }

        #pragma unroll
        for (int kk = 0; kk < 16; kk += 8) {
            // A fragment (m16k8, row-major): conflict-free (pitch-20 bank walk)
            float fa0 = As[cur][mrow    ][kk + t];
            float fa1 = As[cur][mrow + 8][kk + t];
            float fa2 = As[cur][mrow    ][kk + t + 4];
            float fa3 = As[cur][mrow + 8][kk + t + 4];
            uint32_t ah[4], al[4];
            tf32_split(fa0, ah[0], al[0]);
            tf32_split(fa1, ah[1], al[1]);
            tf32_split(fa2, ah[2], al[2]);
            tf32_split(fa3, ah[3], al[3]);
            #pragma unroll
            for (int nt = 0; nt < 4; nt++) {
                float fb0 = Bs[cur][nt * 8 + g][kk + t];
                float fb1 = Bs[cur][nt * 8 + g][kk + t + 4];
                uint32_t bh0, bl0, bh1, bl1;
                tf32_split(fb0, bh0, bl0);
                tf32_split(fb1, bh1, bl1);
                mma_tf32(acc[nt], al, bh0, bh1);   // lo*hi
                mma_tf32(acc[nt], ah, bl0, bl1);   // hi*lo
                mma_tf32(acc[nt], ah, bh0, bh1);   // hi*hi
            }
        }
        // single barrier per chunk: next store targets the other buffer whose
        // readers all finished before THIS chunk's barrier.
    }

    // epilogue: c0=(g,2t) c1=(g,2t+1) c2=(g+8,2t) c3=(g+8,2t+1) per n-tile
    #pragma unroll
    for (int nt = 0; nt < 4; nt++) {
        const int col = j0 + nt * 8 + 2 * t;
        *(float2*)&g_part[kz][mrow    ][col] = make_float2(acc[nt][0], acc[nt][1]);
        *(float2*)&g_part[kz][mrow + 8][col] = make_float2(acc[nt][2], acc[nt][3]);
    }
}

// ============================================================================
// z-split reduce helper: lane = (zq<<3)|jj; each lane sums 4 of 16 z-planes
// for one float4, then 2 shfl_xor rounds (fixed order -> deterministic).
// ============================================================================
static __device__ __forceinline__ float4 zsplit_sum(int cap, int j, int zq) {
    float4 a = make_float4(0.f, 0.f, 0.f, 0.f);
    #pragma unroll
    for (int i = 0; i < 4; i++) {
        float4 p = *(const float4*)&g_part[zq * 4 + i][cap][j];
        a.x += p.x; a.y += p.y; a.z += p.z; a.w += p.w;
    }
    #pragma unroll
    for (int o = 8; o <= 16; o <<= 1) {
        a.x += __shfl_xor_sync(0xffffffffu, a.x, o);
        a.y += __shfl_xor_sync(0xffffffffu, a.y, o);
        a.z += __shfl_xor_sync(0xffffffffu, a.z, o);
        a.w += __shfl_xor_sync(0xffffffffu, a.w, o);
    }
    return a;   // all lanes in the jj-group hold the full 16-z sum
}

// ============================================================================
// reduce_c_norm: out[cap][:] = sum_z g_part[z][cap][:]; g_nrm2[cap][jb] = ||.||^2 part
//   grid (16, 64) = 1024 CTAs, block 128. Warp covers 8 float4 x 16 z.
// ============================================================================
__global__ void __launch_bounds__(128) reduce_c_norm_kernel(float* __restrict__ out) {
    const int cap = blockIdx.y;
    const int jb = blockIdx.x;
    const int tid = threadIdx.x;
    const int w = tid >> 5, lane = tid & 31;
    const int jj = lane & 7, zq = lane >> 3;
    const int j = (jb * 32 + w * 8 + jj) * 4;

    float4 a = zsplit_sum(cap, j, zq);
    if (zq == 0) *(float4*)(out + cap * H_DIM + j) = a;

    // norm partial: every lane has full sum; xor over jj bits sums the 8 j4's
    float sq = a.x * a.x + a.y * a.y + a.z * a.z + a.w * a.w;
    #pragma unroll
    for (int o = 1; o <= 4; o <<= 1) sq += __shfl_xor_sync(0xffffffffu, sq, o);
    __shared__ float ws[4];
    if (lane == 0) ws[w] = sq;
    __syncthreads();
    if (tid == 0) g_nrm2[cap][jb] = (ws[0] + ws[1]) + (ws[2] + ws[3]);
}

// ============================================================================
// squash_scale: coeff from 16 norm partials; scale out row in place. grid 64.
// ============================================================================
__global__ void __launch_bounds__(256) squash_scale_kernel(float* __restrict__ out) {
    const int cap = blockIdx.x;
    const int tid = threadIdx.x;
    __shared__ float coeff_s;
    if (tid == 0) {
        float s = 0.f;
        #pragma unroll
        for (int k = 0; k < 16; k++) s += g_nrm2[cap][k];
        coeff_s = s / (1.0f + s) / sqrtf(s + 1e-9f);
    }
    __syncthreads();
    const float co = coeff_s;
    float* row = out + cap * H_DIM;
    #pragma unroll
    for (int r = 0; r < 2; r++) {
        int j = (tid + 256 * r) * 4;
        float4 v = *(float4*)(row + j);
        *(float4*)(row + j) = make_float4(v.x * co, v.y * co, v.z * co, v.w * co);
    }
}

// ============================================================================
// reduce_v: v[m][:] = sum_z g_part[z][m][:]   (same z-split; grid (16,64))
// ============================================================================
__global__ void __launch_bounds__(128) reduce_v_kernel() {
    const int cap = blockIdx.y;
    const int jb = blockIdx.x;
    const int tid = threadIdx.x;
    const int w = tid >> 5, lane = tid & 31;
    const int jj = lane & 7, zq = lane >> 3;
    const int j = (jb * 32 + w * 8 + jj) * 4;

    float4 a = zsplit_sum(cap, j, zq);
    if (zq == 0) *(float4*)&g_v[cap * H_DIM + j] = a;
}

// ============================================================================
// b_update: b[cap,s] += x[cap,s,:] . v[cap,:]   (warp per s; v staged in smem)
// ============================================================================
__global__ void __launch_bounds__(256) b_update_kernel(const float* __restrict__ x) {
    const int cap = blockIdx.y;
    const int tid = threadIdx.x;
    __shared__ float vs[H_DIM];
    #pragma unroll
    for (int j = 0; j < 2; j++) {
        float4 vv = *(const float4*)(g_v + cap * H_DIM + (tid + 256 * j) * 4);
        *(float4*)(vs + (tid + 256 * j) * 4) = vv;
    }
    __syncthreads();

    const int warp = tid >> 5, lane = tid & 31;
    const int s = blockIdx.x * 8 + warp;
    const float4* xp = (const float4*)(x + ((size_t)cap * S_LEN + s) * H_DIM);
    const float4* vp = (const float4*)vs;
    float acc = 0.f;
    #pragma unroll 4
    for (int j = lane; j < H_DIM / 4; j += 32) {
        float4 ev = xp[j], cv = vp[j];
        acc = fmaf(ev.x, cv.x, acc);
        acc = fmaf(ev.y, cv.y, acc);
        acc = fmaf(ev.z, cv.z, acc);
        acc = fmaf(ev.w, cv.w, acc);
    }
    #pragma unroll
    for (int o = 16; o > 0; o >>= 1) acc += __shfl_xor_sync(0xffffffffu, acc, o);
    if (lane == 0) g_b[cap * S_LEN + s] += acc;
}

// ============================================================================
// kernel_launch
// ============================================================================
extern "C" void kernel_launch(void* const* d_in, const int* in_sizes, int n_in,
                              void* d_out, int out_size) {
    const float* x = (const float*)d_in[0];   // [64,128,2048] fp32
    const float* W = (const float*)d_in[1];   // [2048,2048] fp32
    float* out = (float*)d_out;               // [64,2048] fp32 — holds c

    float* u_ptr;
    cudaGetSymbolAddress((void**)&u_ptr, g_u);

    const dim3 gemm_grid(H_DIM / 32, KSPLIT);

    zero_b_kernel<<<8, 1024>>>();

    for (int it = 0; it < 3; ++it) {
        u_kernel<<<dim3(H_DIM / 256, C_CAPS), 256>>>(x);
        gemm_mma_kernel<false><<<gemm_grid, 128>>>(u_ptr, W);        // c = u @ W
        reduce_c_norm_kernel<<<dim3(16, C_CAPS), 128>>>(out);
        squash_scale_kernel<<<C_CAPS, 256>>>(out);
        if (it < 2) {
            gemm_mma_kernel<true><<<gemm_grid, 128>>>(out, W);       // v = c @ W^T
            reduce_v_kernel<<<dim3(16, C_CAPS), 128>>>();
            b_update_kernel<<<dim3(S_LEN / 8, C_CAPS), 256>>>(x);
        }
    }
}